// round 9
// baseline (speedup 1.0000x reference)
#include <cuda_runtime.h>
#include <cuda_bf16.h>
#include <math.h>
#include <stdint.h>

// ---------------- problem constants ----------------
#define NT    8192
#define DH    2048
#define KW    9
#define PAD   4
#define DIN1  600
#define DINP1 640      // DIN1 padded to multiple of 32
#define DINP2 2048

// ---------------- device-global scratch (no allocation) ----------------
__device__ int            g_seg[NT];
__device__ __nv_bfloat16  g_x1h[(size_t)NT * DINP1];
__device__ __nv_bfloat16  g_x1l[(size_t)NT * DINP1];
__device__ __nv_bfloat16  g_x2h[(size_t)NT * DH];
__device__ __nv_bfloat16  g_x2l[(size_t)NT * DH];
__device__ __nv_bfloat16  g_w1h[(size_t)KW * DH * DINP1];
__device__ __nv_bfloat16  g_w1l[(size_t)KW * DH * DINP1];
__device__ __nv_bfloat16  g_w2h[(size_t)KW * DH * DINP2];
__device__ __nv_bfloat16  g_w2l[(size_t)KW * DH * DINP2];
__device__ float          g_h2[(size_t)NT * DH];

// ---------------- helpers ----------------
__device__ __forceinline__ uint32_t smem_u32(const void* p) {
    uint32_t a;
    asm("{ .reg .u64 t; cvta.to.shared.u64 t, %1; cvt.u32.u64 %0, t; }" : "=r"(a) : "l"(p));
    return a;
}
__device__ __forceinline__ void cp_async16(uint32_t dst, const void* src, uint32_t src_bytes) {
    asm volatile("cp.async.cg.shared.global [%0], [%1], 16, %2;"
                 :: "r"(dst), "l"(src), "r"(src_bytes) : "memory");
}
__device__ __forceinline__ void cp_commit() {
    asm volatile("cp.async.commit_group;" ::: "memory");
}
template<int N>
__device__ __forceinline__ void cp_wait() {
    asm volatile("cp.async.wait_group %0;" :: "n"(N) : "memory");
}
__device__ __forceinline__ void ldmatrix_x4(uint32_t* r, uint32_t addr) {
    asm volatile("ldmatrix.sync.aligned.m8n8.x4.shared.b16 {%0,%1,%2,%3}, [%4];"
                 : "=r"(r[0]), "=r"(r[1]), "=r"(r[2]), "=r"(r[3]) : "r"(addr));
}
__device__ __forceinline__ void mma_bf16(float* c, const uint32_t* a, uint32_t b0, uint32_t b1) {
    asm volatile("mma.sync.aligned.m16n8k16.row.col.f32.bf16.bf16.f32 "
                 "{%0,%1,%2,%3}, {%4,%5,%6,%7}, {%8,%9}, {%0,%1,%2,%3};"
                 : "+f"(c[0]), "+f"(c[1]), "+f"(c[2]), "+f"(c[3])
                 : "r"(a[0]), "r"(a[1]), "r"(a[2]), "r"(a[3]), "r"(b0), "r"(b1));
}

// ============================================================================
// Prep kernels
// ============================================================================
__global__ void normalize_seg_kernel(const int* __restrict__ seg32) {
    bool is64 = (seg32[8191] == 0) && (seg32[4097] == 0) && (seg32[6143] == 0);
    int i = blockIdx.x * blockDim.x + threadIdx.x;
    if (i < NT) g_seg[i] = is64 ? seg32[2 * i] : seg32[i];
}

__global__ void split_x_kernel(const float* __restrict__ x) {
    size_t i = (size_t)blockIdx.x * blockDim.x + threadIdx.x;
    if (i >= (size_t)NT * DINP1) return;
    int c = (int)(i % DINP1);
    int r = (int)(i / DINP1);
    float v = (c < DIN1) ? x[(size_t)r * DIN1 + c] : 0.0f;
    __nv_bfloat16 h = __float2bfloat16(v);
    g_x1h[i] = h;
    g_x1l[i] = __float2bfloat16(v - __bfloat162float(h));
}

// w [DH, din, KW] -> wh/wl [KW][DH][dinp] bf16 (k-contiguous per (tap,n) row)
__global__ void split_w_kernel(const float* __restrict__ w, int din, int dinp, int which, int total) {
    int i = blockIdx.x * blockDim.x + threadIdx.x;   // over DH * dinp
    if (i >= total) return;
    int c = i % dinp;
    int n = i / dinp;
    __nv_bfloat16* oh = (which == 1) ? g_w1h : g_w2h;
    __nv_bfloat16* ol = (which == 1) ? g_w1l : g_w2l;
#pragma unroll
    for (int k = 0; k < KW; ++k) {
        float v = (c < din) ? w[((size_t)n * din + c) * KW + k] : 0.0f;
        __nv_bfloat16 h = __float2bfloat16(v);
        size_t o = ((size_t)k * DH + n) * dinp + c;
        oh[o] = h;
        ol[o] = __float2bfloat16(v - __bfloat162float(h));
    }
}

// ============================================================================
// mma.sync bf16 split-3 conv-GEMM, fused bias+ReLU+BN epilogue.
//   CTA 128x256, 8 warps as 2(M) x 4(N), warp tile 64x64.
//   BK=32, 3-stage cp.async ring, ONE __syncthreads per stage.
//   Segment mask via cp.async zero-fill on A.
// ============================================================================
#define LDROW   80                          // (32+8) bf16 = 80B pitch, LDSM conflict-free
#define ABYTES  (128 * LDROW)               // 10240
#define BBYTES  (256 * LDROW)               // 20480
#define STG     (ABYTES + BBYTES)           // 30720 per stage
#define NSTAGE  3
#define OFF_MSK 0
#define OFF_SC  4608
#define OFF_SH  5632
#define OFF_BB  6656
#define OFF_T   7680                        // tiles base
#define SM_TOTAL (OFF_T + NSTAGE * STG)     // 99840 B -> 2 CTAs/SM

template<int DINP, int LAYER>
__global__ __launch_bounds__(256)
void gemm_mma_kernel(const float* __restrict__ bias, const float* __restrict__ gam,
                     const float* __restrict__ bet,  const float* __restrict__ mu,
                     const float* __restrict__ var)
{
    constexpr int NCH = DINP / 32;
    constexpr int NQ  = 3 * KW * NCH;

    extern __shared__ char smem[];
    const uint32_t sb = smem_u32(smem);
    const int tid  = threadIdx.x;
    const int lane = tid & 31;
    const int wid  = tid >> 5;
    const int row0 = blockIdx.x * 128;
    const int col0 = blockIdx.y * 256;

    float* msk = (float*)(smem + OFF_MSK);
    float* ssc = (float*)(smem + OFF_SC);
    float* ssh = (float*)(smem + OFF_SH);
    float* sbb = (float*)(smem + OFF_BB);

    // segment masks + folded BN params
    for (int t = tid; t < 128 * KW; t += 256) {
        int r = t / KW, k = t - r * KW;
        int src = row0 + r + k - PAD;
        msk[r * KW + k] = (src >= 0 && src < NT && g_seg[src] == g_seg[row0 + r]) ? 1.0f : 0.0f;
    }
    {
        int n = col0 + tid;
        float s = gam[n] * rsqrtf(var[n] + 1e-5f);
        ssc[tid] = s;
        ssh[tid] = bet[n] - mu[n] * s;
        sbb[tid] = bias[n];
    }
    __syncthreads();

    const __nv_bfloat16* Ah = (LAYER == 1) ? g_x1h : g_x2h;
    const __nv_bfloat16* Al = (LAYER == 1) ? g_x1l : g_x2l;
    const __nv_bfloat16* Bh = (LAYER == 1) ? g_w1h : g_w2h;
    const __nv_bfloat16* Bl = (LAYER == 1) ? g_w1l : g_w2l;

    // ---- load mapping ----
    // A: 128 rows x 64B; 2 threads/row, 32B (2 x 16B) each
    const int  ldrA  = tid >> 1;
    const int  ldcbA = (tid & 1) * 32;       // byte offset in row
    const int  ldceA = (tid & 1) * 16;       // element offset
    // B: 256 rows x 64B; 1 thread/row, 64B (4 x 16B)
    const int  ldrB  = tid;
    const uint32_t dstA0 = sb + OFF_T + ldrA * LDROW + ldcbA;
    const uint32_t dstB0 = sb + OFF_T + ABYTES + ldrB * LDROW;

    // ---- compute mapping: warps 2(M) x 4(N), warp tile 64x64 ----
    const int wm = (wid >> 2) * 64;
    const int wn = (wid & 3) * 64;
    uint32_t aAddr[4], bAddr[4];
#pragma unroll
    for (int mb = 0; mb < 4; ++mb)
        aAddr[mb] = sb + OFF_T + (wm + mb * 16 + (lane & 15)) * LDROW + ((lane >> 4) & 1) * 16;
#pragma unroll
    for (int nq = 0; nq < 4; ++nq)
        bAddr[nq] = sb + OFF_T + ABYTES + (wn + nq * 16 + (lane & 15)) * LDROW + ((lane >> 4) & 1) * 16;

    float acc[4][8][4];
#pragma unroll
    for (int mb = 0; mb < 4; ++mb)
#pragma unroll
        for (int nb = 0; nb < 8; ++nb)
#pragma unroll
            for (int d = 0; d < 4; ++d) acc[mb][nb][d] = 0.0f;

    // ---- stage loader ----
    auto load_stage = [&](int q, int st) {
        int pass = q / (KW * NCH);
        int rem  = q - pass * (KW * NCH);
        int tap  = rem / NCH;
        int c0   = (rem - tap * NCH) * 32;
        const __nv_bfloat16* Ap = (pass == 1) ? Al : Ah;   // hh, lh, hl
        const __nv_bfloat16* Bp = (pass == 2) ? Bl : Bh;

        int srow = row0 + ldrA + tap - PAD;
        srow = srow < 0 ? 0 : (srow > NT - 1 ? NT - 1 : srow);
        uint32_t asz = (msk[ldrA * KW + tap] != 0.0f) ? 16u : 0u;
        const __nv_bfloat16* sa = Ap + (size_t)srow * DINP + c0 + ldceA;
        uint32_t da = dstA0 + st * STG;
        cp_async16(da,      sa,     asz);
        cp_async16(da + 16, sa + 8, asz);

        const __nv_bfloat16* sbp = Bp + ((size_t)tap * DH + col0 + ldrB) * DINP + c0;
        uint32_t db = dstB0 + st * STG;
#pragma unroll
        for (int ch = 0; ch < 4; ++ch)
            cp_async16(db + ch * 16, sbp + ch * 8, 16u);
    };

    // ---- prologue: fill NSTAGE-1 stages ----
    load_stage(0, 0); cp_commit();
    load_stage(1, 1); cp_commit();

    // ---- mainloop: one __syncthreads per stage ----
#pragma unroll 1
    for (int q = 0; q < NQ; ++q) {
        const int st = q % NSTAGE;
        cp_wait<NSTAGE - 2>();
        __syncthreads();                       // stage q visible; stage (q-1)%NSTAGE free
        if (q + NSTAGE - 1 < NQ) load_stage(q + NSTAGE - 1, (q + NSTAGE - 1) % NSTAGE);
        cp_commit();                           // unconditional: keeps wait-count invariant

        const uint32_t so = st * STG;
#pragma unroll
        for (int ks = 0; ks < 2; ++ks) {       // BK=32 -> 2 x k16
            uint32_t afr[4][4], bfr[4][4];
#pragma unroll
            for (int mb = 0; mb < 4; ++mb) ldmatrix_x4(afr[mb], aAddr[mb] + so + ks * 32);
#pragma unroll
            for (int nq = 0; nq < 4; ++nq) ldmatrix_x4(bfr[nq], bAddr[nq] + so + ks * 32);
            // bfr regs: r0=n[0:8]k[0:8], r1=n[8:16]k[0:8], r2=n[0:8]k[8:16], r3=n[8:16]k[8:16]
#pragma unroll
            for (int mb = 0; mb < 4; ++mb)
#pragma unroll
                for (int nb = 0; nb < 8; ++nb) {
                    int nq = nb >> 1;
                    if (nb & 1) mma_bf16(acc[mb][nb], afr[mb], bfr[nq][1], bfr[nq][3]);
                    else        mma_bf16(acc[mb][nb], afr[mb], bfr[nq][0], bfr[nq][2]);
                }
        }
    }

    // -------- epilogue: y = relu(acc+b)*sc+sh; layer1 emits bf16 split pair --------
    const int erow = lane >> 2;           // 0..7
    const int ecol = (lane & 3) * 2;      // 0,2,4,6
#pragma unroll
    for (int mb = 0; mb < 4; ++mb) {
#pragma unroll
        for (int nb = 0; nb < 8; ++nb) {
#pragma unroll
            for (int half = 0; half < 2; ++half) {
                int r  = row0 + wm + mb * 16 + erow + half * 8;
                int cl = wn + nb * 8 + ecol;            // local col in [0,256)
                float y0 = fmaxf(acc[mb][nb][half * 2 + 0] + sbb[cl],     0.0f) * ssc[cl]     + ssh[cl];
                float y1 = fmaxf(acc[mb][nb][half * 2 + 1] + sbb[cl + 1], 0.0f) * ssc[cl + 1] + ssh[cl + 1];
                if (LAYER == 1) {
                    __nv_bfloat16 h0 = __float2bfloat16(y0);
                    __nv_bfloat16 h1 = __float2bfloat16(y1);
                    __nv_bfloat162 hv; hv.x = h0; hv.y = h1;
                    __nv_bfloat162 lv;
                    lv.x = __float2bfloat16(y0 - __bfloat162float(h0));
                    lv.y = __float2bfloat16(y1 - __bfloat162float(h1));
                    *(__nv_bfloat162*)(g_x2h + (size_t)r * DH + col0 + cl) = hv;
                    *(__nv_bfloat162*)(g_x2l + (size_t)r * DH + col0 + cl) = lv;
                } else {
                    float2 v; v.x = y0; v.y = y1;
                    *(float2*)(g_h2 + (size_t)r * DH + col0 + cl) = v;
                }
            }
        }
    }
}

// ============================================================================
// Head: logits = h2 @ w_lin^T + b_lin ; probs = softmax. One warp per row.
// ============================================================================
__global__ void head_kernel(const float* __restrict__ wlin, const float* __restrict__ blin,
                            float* __restrict__ out, int out_elems)
{
    int gtid = blockIdx.x * blockDim.x + threadIdx.x;
    int row = gtid >> 5, lane = gtid & 31;
    if (row >= NT) return;
    const float* hr = g_h2 + (size_t)row * DH;
    float s0 = 0.0f, s1 = 0.0f;
    for (int j = lane; j < DH; j += 32) {
        float x = hr[j];
        s0 = fmaf(x, wlin[j], s0);
        s1 = fmaf(x, wlin[DH + j], s1);
    }
#pragma unroll
    for (int o = 16; o > 0; o >>= 1) {
        s0 += __shfl_down_sync(0xFFFFFFFFu, s0, o);
        s1 += __shfl_down_sync(0xFFFFFFFFu, s1, o);
    }
    if (lane == 0) {
        float o0 = s0 + blin[0], o1 = s1 + blin[1];
        out[2 * row] = o0;
        out[2 * row + 1] = o1;
        if (out_elems >= 4 * NT) {
            float mx = fmaxf(o0, o1);
            float e0 = expf(o0 - mx), e1 = expf(o1 - mx);
            float inv = 1.0f / (e0 + e1);
            out[2 * NT + 2 * row]     = e0 * inv;
            out[2 * NT + 2 * row + 1] = e1 * inv;
        }
    }
}

// ============================================================================
extern "C" void kernel_launch(void* const* d_in, const int* in_sizes, int n_in,
                              void* d_out, int out_size)
{
    const float* latent = (const float*) d_in[0];
    const int*   seg    = (const int*)   d_in[1];
    const float* w1     = (const float*) d_in[2];
    const float* b1     = (const float*) d_in[3];
    const float* g1     = (const float*) d_in[4];
    const float* be1    = (const float*) d_in[5];
    const float* m1     = (const float*) d_in[6];
    const float* v1     = (const float*) d_in[7];
    const float* w2     = (const float*) d_in[8];
    const float* b2     = (const float*) d_in[9];
    const float* g2     = (const float*) d_in[10];
    const float* be2    = (const float*) d_in[11];
    const float* m2     = (const float*) d_in[12];
    const float* v2     = (const float*) d_in[13];
    const float* wlin   = (const float*) d_in[14];
    const float* blin   = (const float*) d_in[15];
    float*       out    = (float*)       d_out;

    normalize_seg_kernel<<<(NT + 255) / 256, 256>>>(seg);

    size_t nx = (size_t)NT * DINP1;
    split_x_kernel<<<(unsigned)((nx + 255) / 256), 256>>>(latent);
    int nw1 = DH * DINP1;
    int nw2 = DH * DINP2;
    split_w_kernel<<<(nw1 + 255) / 256, 256>>>(w1, DIN1, DINP1, 1, nw1);
    split_w_kernel<<<(nw2 + 255) / 256, 256>>>(w2, DH,   DINP2, 2, nw2);

    cudaFuncSetAttribute(gemm_mma_kernel<DINP1, 1>,
                         cudaFuncAttributeMaxDynamicSharedMemorySize, SM_TOTAL);
    cudaFuncSetAttribute(gemm_mma_kernel<DINP2, 2>,
                         cudaFuncAttributeMaxDynamicSharedMemorySize, SM_TOTAL);

    dim3 grid(NT / 128, DH / 256);   // x fastest -> CTAs sharing a B panel run together
    gemm_mma_kernel<DINP1, 1><<<grid, 256, SM_TOTAL>>>(b1, g1, be1, m1, v1);
    gemm_mma_kernel<DINP2, 2><<<grid, 256, SM_TOTAL>>>(b2, g2, be2, m2, v2);

    head_kernel<<<(NT * 32 + 255) / 256, 256>>>(wlin, blin, out, out_size);
}

// round 12
// speedup vs baseline: 1.3208x; 1.3208x over previous
#include <cuda_runtime.h>
#include <cuda_bf16.h>
#include <math.h>
#include <stdint.h>

// ---------------- problem constants ----------------
#define NT    8192
#define DH    2048
#define KW    9
#define PAD   4
#define DIN1  600
#define DINP1 640      // DIN1 padded to multiple of 32
#define DINP2 2048

// ---------------- device-global scratch (no allocation) ----------------
__device__ int            g_seg[NT];
__device__ __nv_bfloat16  g_x1h[(size_t)NT * DINP1];
__device__ __nv_bfloat16  g_x1l[(size_t)NT * DINP1];
__device__ __nv_bfloat16  g_x2h[(size_t)NT * DH];
__device__ __nv_bfloat16  g_x2l[(size_t)NT * DH];
__device__ __nv_bfloat16  g_w1h[(size_t)KW * DH * DINP1];
__device__ __nv_bfloat16  g_w1l[(size_t)KW * DH * DINP1];
__device__ __nv_bfloat16  g_w2h[(size_t)KW * DH * DINP2];
__device__ __nv_bfloat16  g_w2l[(size_t)KW * DH * DINP2];
__device__ float          g_h2[(size_t)NT * DH];

// ---------------- helpers ----------------
__device__ __forceinline__ uint32_t smem_u32(const void* p) {
    uint32_t a;
    asm("{ .reg .u64 t; cvta.to.shared.u64 t, %1; cvt.u32.u64 %0, t; }" : "=r"(a) : "l"(p));
    return a;
}
__device__ __forceinline__ void cp_async16(uint32_t dst, const void* src, uint32_t src_bytes) {
    asm volatile("cp.async.cg.shared.global [%0], [%1], 16, %2;"
                 :: "r"(dst), "l"(src), "r"(src_bytes) : "memory");
}
__device__ __forceinline__ void cp_commit() {
    asm volatile("cp.async.commit_group;" ::: "memory");
}
template<int N>
__device__ __forceinline__ void cp_wait() {
    asm volatile("cp.async.wait_group %0;" :: "n"(N) : "memory");
}
__device__ __forceinline__ void ldmatrix_x4(uint32_t* r, uint32_t addr) {
    asm volatile("ldmatrix.sync.aligned.m8n8.x4.shared.b16 {%0,%1,%2,%3}, [%4];"
                 : "=r"(r[0]), "=r"(r[1]), "=r"(r[2]), "=r"(r[3]) : "r"(addr));
}
__device__ __forceinline__ void mma_bf16(float* c, const uint32_t* a, uint32_t b0, uint32_t b1) {
    asm volatile("mma.sync.aligned.m16n8k16.row.col.f32.bf16.bf16.f32 "
                 "{%0,%1,%2,%3}, {%4,%5,%6,%7}, {%8,%9}, {%0,%1,%2,%3};"
                 : "+f"(c[0]), "+f"(c[1]), "+f"(c[2]), "+f"(c[3])
                 : "r"(a[0]), "r"(a[1]), "r"(a[2]), "r"(a[3]), "r"(b0), "r"(b1));
}

// ============================================================================
// Prep kernels
// ============================================================================
__global__ void normalize_seg_kernel(const int* __restrict__ seg32) {
    bool is64 = (seg32[8191] == 0) && (seg32[4097] == 0) && (seg32[6143] == 0);
    int i = blockIdx.x * blockDim.x + threadIdx.x;
    if (i < NT) g_seg[i] = is64 ? seg32[2 * i] : seg32[i];
}

__global__ void split_x_kernel(const float* __restrict__ x) {
    size_t i = (size_t)blockIdx.x * blockDim.x + threadIdx.x;
    if (i >= (size_t)NT * DINP1) return;
    int c = (int)(i % DINP1);
    int r = (int)(i / DINP1);
    float v = (c < DIN1) ? x[(size_t)r * DIN1 + c] : 0.0f;
    __nv_bfloat16 h = __float2bfloat16(v);
    g_x1h[i] = h;
    g_x1l[i] = __float2bfloat16(v - __bfloat162float(h));
}

// w [DH, din, KW] -> wh/wl [KW][DH][dinp] bf16 (k-contiguous per (tap,n) row)
__global__ void split_w_kernel(const float* __restrict__ w, int din, int dinp, int which, int total) {
    int i = blockIdx.x * blockDim.x + threadIdx.x;   // over DH * dinp
    if (i >= total) return;
    int c = i % dinp;
    int n = i / dinp;
    __nv_bfloat16* oh = (which == 1) ? g_w1h : g_w2h;
    __nv_bfloat16* ol = (which == 1) ? g_w1l : g_w2l;
#pragma unroll
    for (int k = 0; k < KW; ++k) {
        float v = (c < din) ? w[((size_t)n * din + c) * KW + k] : 0.0f;
        __nv_bfloat16 h = __float2bfloat16(v);
        size_t o = ((size_t)k * DH + n) * dinp + c;
        oh[o] = h;
        ol[o] = __float2bfloat16(v - __bfloat162float(h));
    }
}

// ============================================================================
// mma.sync bf16 split-3 conv-GEMM, fused bias+ReLU+BN epilogue.
//   CTA 128x128 (R8 tile -> 2 CTAs/SM), 8 warps as 2(M) x 4(N), warp 64x32.
//   BK=32, 4-stage cp.async ring, ONE __syncthreads per stage (R9 pipeline).
//   Segment mask via cp.async zero-fill on A.
// ============================================================================
#define LDROW   80                          // (32+8) bf16 = 80B pitch, LDSM conflict-free
#define ABYTES  (128 * LDROW)               // 10240
#define STG     (2 * ABYTES)                // 20480 per stage (A + B)
#define NSTAGE  4
#define OFF_MSK 0
#define OFF_SC  4608
#define OFF_SH  5120
#define OFF_BB  5632
#define OFF_T   6144                        // tiles base
#define SM_TOTAL (OFF_T + NSTAGE * STG)     // 88064 B -> 2 CTAs/SM

template<int DINP, int LAYER>
__global__ __launch_bounds__(256, 2)
void gemm_mma_kernel(const float* __restrict__ bias, const float* __restrict__ gam,
                     const float* __restrict__ bet,  const float* __restrict__ mu,
                     const float* __restrict__ var)
{
    constexpr int NCH = DINP / 32;
    constexpr int NQ  = 3 * KW * NCH;

    extern __shared__ char smem[];
    const uint32_t sb = smem_u32(smem);
    const int tid  = threadIdx.x;
    const int lane = tid & 31;
    const int wid  = tid >> 5;
    const int row0 = blockIdx.x * 128;
    const int col0 = blockIdx.y * 128;

    float* msk = (float*)(smem + OFF_MSK);
    float* ssc = (float*)(smem + OFF_SC);
    float* ssh = (float*)(smem + OFF_SH);
    float* sbb = (float*)(smem + OFF_BB);

    // segment masks + folded BN params
    for (int t = tid; t < 128 * KW; t += 256) {
        int r = t / KW, k = t - r * KW;
        int src = row0 + r + k - PAD;
        msk[r * KW + k] = (src >= 0 && src < NT && g_seg[src] == g_seg[row0 + r]) ? 1.0f : 0.0f;
    }
    if (tid < 128) {
        int n = col0 + tid;
        float s = gam[n] * rsqrtf(var[n] + 1e-5f);
        ssc[tid] = s;
        ssh[tid] = bet[n] - mu[n] * s;
        sbb[tid] = bias[n];
    }
    __syncthreads();

    const __nv_bfloat16* Ah = (LAYER == 1) ? g_x1h : g_x2h;
    const __nv_bfloat16* Al = (LAYER == 1) ? g_x1l : g_x2l;
    const __nv_bfloat16* Bh = (LAYER == 1) ? g_w1h : g_w2h;
    const __nv_bfloat16* Bl = (LAYER == 1) ? g_w1l : g_w2l;

    // ---- load mapping: 128 rows x 64B per operand; 2 threads/row, 32B each ----
    const int  ldr   = tid >> 1;              // 0..127
    const int  ldcb  = (tid & 1) * 32;        // byte offset in row
    const int  ldce  = (tid & 1) * 16;        // element offset
    const uint32_t dstA0 = sb + OFF_T + ldr * LDROW + ldcb;
    const uint32_t dstB0 = sb + OFF_T + ABYTES + ldr * LDROW + ldcb;

    // ---- compute mapping: warps 2(M) x 4(N), warp tile 64x32 ----
    const int wm = (wid >> 2) * 64;
    const int wn = (wid & 3) * 32;
    uint32_t aAddr[4], bAddr[2];
#pragma unroll
    for (int mb = 0; mb < 4; ++mb)
        aAddr[mb] = sb + OFF_T + (wm + mb * 16 + (lane & 15)) * LDROW + ((lane >> 4) & 1) * 16;
#pragma unroll
    for (int nq = 0; nq < 2; ++nq)
        bAddr[nq] = sb + OFF_T + ABYTES + (wn + nq * 16 + (lane & 15)) * LDROW + ((lane >> 4) & 1) * 16;

    float acc[4][4][4];
#pragma unroll
    for (int mb = 0; mb < 4; ++mb)
#pragma unroll
        for (int nb = 0; nb < 4; ++nb)
#pragma unroll
            for (int d = 0; d < 4; ++d) acc[mb][nb][d] = 0.0f;

    // ---- stage loader ----
    auto load_stage = [&](int q, int st) {
        int pass = q / (KW * NCH);
        int rem  = q - pass * (KW * NCH);
        int tap  = rem / NCH;
        int c0   = (rem - tap * NCH) * 32;
        const __nv_bfloat16* Ap = (pass == 1) ? Al : Ah;   // hh, lh, hl
        const __nv_bfloat16* Bp = (pass == 2) ? Bl : Bh;

        int srow = row0 + ldr + tap - PAD;
        srow = srow < 0 ? 0 : (srow > NT - 1 ? NT - 1 : srow);
        uint32_t asz = (msk[ldr * KW + tap] != 0.0f) ? 16u : 0u;
        const __nv_bfloat16* sa = Ap + (size_t)srow * DINP + c0 + ldce;
        uint32_t da = dstA0 + st * STG;
        cp_async16(da,      sa,     asz);
        cp_async16(da + 16, sa + 8, asz);

        const __nv_bfloat16* sbp = Bp + ((size_t)tap * DH + col0 + ldr) * DINP + c0 + ldce;
        uint32_t db = dstB0 + st * STG;
        cp_async16(db,      sbp,     16u);
        cp_async16(db + 16, sbp + 8, 16u);
    };

    // ---- prologue: fill NSTAGE-1 stages ----
    load_stage(0, 0); cp_commit();
    load_stage(1, 1); cp_commit();
    load_stage(2, 2); cp_commit();

    // ---- mainloop: one __syncthreads per stage ----
#pragma unroll 1
    for (int q = 0; q < NQ; ++q) {
        const int st = q % NSTAGE;
        cp_wait<NSTAGE - 2>();
        __syncthreads();                       // stage q visible; slot (q+3)%4 = (q-1)%4 free
        if (q + NSTAGE - 1 < NQ) load_stage(q + NSTAGE - 1, (q + NSTAGE - 1) % NSTAGE);
        cp_commit();                           // unconditional: keeps wait-count invariant

        const uint32_t so = st * STG;
#pragma unroll
        for (int ks = 0; ks < 2; ++ks) {       // BK=32 -> 2 x k16
            uint32_t afr[4][4], bfr[2][4];
#pragma unroll
            for (int mb = 0; mb < 4; ++mb) ldmatrix_x4(afr[mb], aAddr[mb] + so + ks * 32);
#pragma unroll
            for (int nq = 0; nq < 2; ++nq) ldmatrix_x4(bfr[nq], bAddr[nq] + so + ks * 32);
            // bfr regs: r0=n[0:8]k[0:8], r1=n[8:16]k[0:8], r2=n[0:8]k[8:16], r3=n[8:16]k[8:16]
#pragma unroll
            for (int mb = 0; mb < 4; ++mb)
#pragma unroll
                for (int nb = 0; nb < 4; ++nb) {
                    int nq = nb >> 1;
                    if (nb & 1) mma_bf16(acc[mb][nb], afr[mb], bfr[nq][1], bfr[nq][3]);
                    else        mma_bf16(acc[mb][nb], afr[mb], bfr[nq][0], bfr[nq][2]);
                }
        }
    }

    // -------- epilogue: y = relu(acc+b)*sc+sh; layer1 emits bf16 split pair --------
    const int erow = lane >> 2;           // 0..7
    const int ecol = (lane & 3) * 2;      // 0,2,4,6
#pragma unroll
    for (int mb = 0; mb < 4; ++mb) {
#pragma unroll
        for (int nb = 0; nb < 4; ++nb) {
#pragma unroll
            for (int half = 0; half < 2; ++half) {
                int r  = row0 + wm + mb * 16 + erow + half * 8;
                int cl = wn + nb * 8 + ecol;            // local col in [0,128)
                float y0 = fmaxf(acc[mb][nb][half * 2 + 0] + sbb[cl],     0.0f) * ssc[cl]     + ssh[cl];
                float y1 = fmaxf(acc[mb][nb][half * 2 + 1] + sbb[cl + 1], 0.0f) * ssc[cl + 1] + ssh[cl + 1];
                if (LAYER == 1) {
                    __nv_bfloat16 h0 = __float2bfloat16(y0);
                    __nv_bfloat16 h1 = __float2bfloat16(y1);
                    __nv_bfloat162 hv; hv.x = h0; hv.y = h1;
                    __nv_bfloat162 lv;
                    lv.x = __float2bfloat16(y0 - __bfloat162float(h0));
                    lv.y = __float2bfloat16(y1 - __bfloat162float(h1));
                    *(__nv_bfloat162*)(g_x2h + (size_t)r * DH + col0 + cl) = hv;
                    *(__nv_bfloat162*)(g_x2l + (size_t)r * DH + col0 + cl) = lv;
                } else {
                    float2 v; v.x = y0; v.y = y1;
                    *(float2*)(g_h2 + (size_t)r * DH + col0 + cl) = v;
                }
            }
        }
    }
}

// ============================================================================
// Head: logits = h2 @ w_lin^T + b_lin ; probs = softmax. One warp per row.
// ============================================================================
__global__ void head_kernel(const float* __restrict__ wlin, const float* __restrict__ blin,
                            float* __restrict__ out, int out_elems)
{
    int gtid = blockIdx.x * blockDim.x + threadIdx.x;
    int row = gtid >> 5, lane = gtid & 31;
    if (row >= NT) return;
    const float* hr = g_h2 + (size_t)row * DH;
    float s0 = 0.0f, s1 = 0.0f;
    for (int j = lane; j < DH; j += 32) {
        float x = hr[j];
        s0 = fmaf(x, wlin[j], s0);
        s1 = fmaf(x, wlin[DH + j], s1);
    }
#pragma unroll
    for (int o = 16; o > 0; o >>= 1) {
        s0 += __shfl_down_sync(0xFFFFFFFFu, s0, o);
        s1 += __shfl_down_sync(0xFFFFFFFFu, s1, o);
    }
    if (lane == 0) {
        float o0 = s0 + blin[0], o1 = s1 + blin[1];
        out[2 * row] = o0;
        out[2 * row + 1] = o1;
        if (out_elems >= 4 * NT) {
            float mx = fmaxf(o0, o1);
            float e0 = expf(o0 - mx), e1 = expf(o1 - mx);
            float inv = 1.0f / (e0 + e1);
            out[2 * NT + 2 * row]     = e0 * inv;
            out[2 * NT + 2 * row + 1] = e1 * inv;
        }
    }
}

// ============================================================================
extern "C" void kernel_launch(void* const* d_in, const int* in_sizes, int n_in,
                              void* d_out, int out_size)
{
    const float* latent = (const float*) d_in[0];
    const int*   seg    = (const int*)   d_in[1];
    const float* w1     = (const float*) d_in[2];
    const float* b1     = (const float*) d_in[3];
    const float* g1     = (const float*) d_in[4];
    const float* be1    = (const float*) d_in[5];
    const float* m1     = (const float*) d_in[6];
    const float* v1     = (const float*) d_in[7];
    const float* w2     = (const float*) d_in[8];
    const float* b2     = (const float*) d_in[9];
    const float* g2     = (const float*) d_in[10];
    const float* be2    = (const float*) d_in[11];
    const float* m2     = (const float*) d_in[12];
    const float* v2     = (const float*) d_in[13];
    const float* wlin   = (const float*) d_in[14];
    const float* blin   = (const float*) d_in[15];
    float*       out    = (float*)       d_out;

    normalize_seg_kernel<<<(NT + 255) / 256, 256>>>(seg);

    size_t nx = (size_t)NT * DINP1;
    split_x_kernel<<<(unsigned)((nx + 255) / 256), 256>>>(latent);
    int nw1 = DH * DINP1;
    int nw2 = DH * DINP2;
    split_w_kernel<<<(nw1 + 255) / 256, 256>>>(w1, DIN1, DINP1, 1, nw1);
    split_w_kernel<<<(nw2 + 255) / 256, 256>>>(w2, DH,   DINP2, 2, nw2);

    cudaFuncSetAttribute(gemm_mma_kernel<DINP1, 1>,
                         cudaFuncAttributeMaxDynamicSharedMemorySize, SM_TOTAL);
    cudaFuncSetAttribute(gemm_mma_kernel<DINP2, 2>,
                         cudaFuncAttributeMaxDynamicSharedMemorySize, SM_TOTAL);

    dim3 grid(NT / 128, DH / 128);   // x fastest -> CTAs sharing a B panel run together
    gemm_mma_kernel<DINP1, 1><<<grid, 256, SM_TOTAL>>>(b1, g1, be1, m1, v1);
    gemm_mma_kernel<DINP2, 2><<<grid, 256, SM_TOTAL>>>(b2, g2, be2, m2, v2);

    head_kernel<<<(NT * 32 + 255) / 256, 256>>>(wlin, blin, out, out_size);
}

// round 13
// speedup vs baseline: 1.5541x; 1.1766x over previous
#include <cuda_runtime.h>
#include <cuda_bf16.h>
#include <math.h>
#include <stdint.h>

// ---------------- problem constants ----------------
#define NT    8192
#define DH    2048
#define KW    9
#define PAD   4
#define DIN1  600
#define DINP1 640      // DIN1 padded to multiple of 32
#define DINP2 2048

// ---------------- device-global scratch (no allocation) ----------------
__device__ int            g_seg[NT];
__device__ __nv_bfloat16  g_x1h[(size_t)NT * DINP1];
__device__ __nv_bfloat16  g_x1l[(size_t)NT * DINP1];
__device__ __nv_bfloat16  g_x2h[(size_t)NT * DH];
__device__ __nv_bfloat16  g_x2l[(size_t)NT * DH];
__device__ __nv_bfloat16  g_w1h[(size_t)KW * DH * DINP1];
__device__ __nv_bfloat16  g_w1l[(size_t)KW * DH * DINP1];
__device__ __nv_bfloat16  g_w2h[(size_t)KW * DH * DINP2];
__device__ __nv_bfloat16  g_w2l[(size_t)KW * DH * DINP2];
__device__ float          g_h2[(size_t)NT * DH];

// ---------------- helpers ----------------
__device__ __forceinline__ uint32_t smem_u32(const void* p) {
    uint32_t a;
    asm("{ .reg .u64 t; cvta.to.shared.u64 t, %1; cvt.u32.u64 %0, t; }" : "=r"(a) : "l"(p));
    return a;
}
__device__ __forceinline__ void cp_async16(uint32_t dst, const void* src, uint32_t src_bytes) {
    asm volatile("cp.async.cg.shared.global [%0], [%1], 16, %2;"
                 :: "r"(dst), "l"(src), "r"(src_bytes) : "memory");
}
__device__ __forceinline__ void cp_commit() {
    asm volatile("cp.async.commit_group;" ::: "memory");
}
template<int N>
__device__ __forceinline__ void cp_wait() {
    asm volatile("cp.async.wait_group %0;" :: "n"(N) : "memory");
}
__device__ __forceinline__ void ldmatrix_x4(uint32_t* r, uint32_t addr) {
    asm volatile("ldmatrix.sync.aligned.m8n8.x4.shared.b16 {%0,%1,%2,%3}, [%4];"
                 : "=r"(r[0]), "=r"(r[1]), "=r"(r[2]), "=r"(r[3]) : "r"(addr));
}
__device__ __forceinline__ void mma_bf16(float* c, const uint32_t* a, uint32_t b0, uint32_t b1) {
    asm volatile("mma.sync.aligned.m16n8k16.row.col.f32.bf16.bf16.f32 "
                 "{%0,%1,%2,%3}, {%4,%5,%6,%7}, {%8,%9}, {%0,%1,%2,%3};"
                 : "+f"(c[0]), "+f"(c[1]), "+f"(c[2]), "+f"(c[3])
                 : "r"(a[0]), "r"(a[1]), "r"(a[2]), "r"(a[3]), "r"(b0), "r"(b1));
}

// ============================================================================
// Prep kernels
// ============================================================================
__global__ void normalize_seg_kernel(const int* __restrict__ seg32) {
    bool is64 = (seg32[8191] == 0) && (seg32[4097] == 0) && (seg32[6143] == 0);
    int i = blockIdx.x * blockDim.x + threadIdx.x;
    if (i < NT) g_seg[i] = is64 ? seg32[2 * i] : seg32[i];
}

__global__ void split_x_kernel(const float* __restrict__ x) {
    size_t i = (size_t)blockIdx.x * blockDim.x + threadIdx.x;
    if (i >= (size_t)NT * DINP1) return;
    int c = (int)(i % DINP1);
    int r = (int)(i / DINP1);
    float v = (c < DIN1) ? x[(size_t)r * DIN1 + c] : 0.0f;
    __nv_bfloat16 h = __float2bfloat16(v);
    g_x1h[i] = h;
    g_x1l[i] = __float2bfloat16(v - __bfloat162float(h));
}

// w [DH, din, KW] -> wh/wl [KW][DH][dinp] bf16 (k-contiguous per (tap,n) row)
__global__ void split_w_kernel(const float* __restrict__ w, int din, int dinp, int which, int total) {
    int i = blockIdx.x * blockDim.x + threadIdx.x;   // over DH * dinp
    if (i >= total) return;
    int c = i % dinp;
    int n = i / dinp;
    __nv_bfloat16* oh = (which == 1) ? g_w1h : g_w2h;
    __nv_bfloat16* ol = (which == 1) ? g_w1l : g_w2l;
#pragma unroll
    for (int k = 0; k < KW; ++k) {
        float v = (c < din) ? w[((size_t)n * din + c) * KW + k] : 0.0f;
        __nv_bfloat16 h = __float2bfloat16(v);
        size_t o = ((size_t)k * DH + n) * dinp + c;
        oh[o] = h;
        ol[o] = __float2bfloat16(v - __bfloat162float(h));
    }
}

// ============================================================================
// mma.sync bf16 FUSED split-3 conv-GEMM, fused bias+ReLU+BN epilogue.
//   CTA 128x128, 8 warps as 2(M) x 4(N), warp tile 64x32.
//   Stage = {Ah, Al, Bh, Bl} for one (tap, 32-chunk); all 3 split products
//   (hh, hl, lh) computed per stage -> 4 tile-loads per 3 products instead
//   of 6.  BK=32, 2-stage ring, ONE __syncthreads per stage.
//   Segment mask via cp.async zero-fill on A.
// ============================================================================
#define LDROW   80                          // (32+8) bf16 = 80B pitch, LDSM conflict-free
#define ABYTES  (128 * LDROW)               // 10240 per tile
#define STG     (4 * ABYTES)                // 40960 per stage (Ah, Al, Bh, Bl)
#define NSTAGE  2
#define OFF_MSK 0
#define OFF_SC  4608
#define OFF_SH  5120
#define OFF_BB  5632
#define OFF_T   6144                        // tiles base
#define SM_TOTAL (OFF_T + NSTAGE * STG)     // 88064 B -> 2 CTAs/SM

template<int DINP, int LAYER>
__global__ __launch_bounds__(256, 2)
void gemm_mma_kernel(const float* __restrict__ bias, const float* __restrict__ gam,
                     const float* __restrict__ bet,  const float* __restrict__ mu,
                     const float* __restrict__ var)
{
    constexpr int NCH = DINP / 32;
    constexpr int NQ  = KW * NCH;           // one stage per (tap, chunk)

    extern __shared__ char smem[];
    const uint32_t sb = smem_u32(smem);
    const int tid  = threadIdx.x;
    const int lane = tid & 31;
    const int wid  = tid >> 5;
    const int row0 = blockIdx.x * 128;
    const int col0 = blockIdx.y * 128;

    float* msk = (float*)(smem + OFF_MSK);
    float* ssc = (float*)(smem + OFF_SC);
    float* ssh = (float*)(smem + OFF_SH);
    float* sbb = (float*)(smem + OFF_BB);

    // segment masks + folded BN params
    for (int t = tid; t < 128 * KW; t += 256) {
        int r = t / KW, k = t - r * KW;
        int src = row0 + r + k - PAD;
        msk[r * KW + k] = (src >= 0 && src < NT && g_seg[src] == g_seg[row0 + r]) ? 1.0f : 0.0f;
    }
    if (tid < 128) {
        int n = col0 + tid;
        float s = gam[n] * rsqrtf(var[n] + 1e-5f);
        ssc[tid] = s;
        ssh[tid] = bet[n] - mu[n] * s;
        sbb[tid] = bias[n];
    }
    __syncthreads();

    const __nv_bfloat16* Ah = (LAYER == 1) ? g_x1h : g_x2h;
    const __nv_bfloat16* Al = (LAYER == 1) ? g_x1l : g_x2l;
    const __nv_bfloat16* Bh = (LAYER == 1) ? g_w1h : g_w2h;
    const __nv_bfloat16* Bl = (LAYER == 1) ? g_w1l : g_w2l;

    // ---- load mapping: 128 rows x 64B per tile; 2 threads/row, 32B each ----
    const int  ldr   = tid >> 1;              // 0..127
    const int  ldcb  = (tid & 1) * 32;        // byte offset in row
    const int  ldce  = (tid & 1) * 16;        // element offset
    const uint32_t dst0 = sb + OFF_T + ldr * LDROW + ldcb;

    // ---- compute mapping: warps 2(M) x 4(N), warp tile 64x32 ----
    const int wm = (wid >> 2) * 64;
    const int wn = (wid & 3) * 32;
    uint32_t aAddr[4], bAddr[2];
#pragma unroll
    for (int mb = 0; mb < 4; ++mb)
        aAddr[mb] = sb + OFF_T + (wm + mb * 16 + (lane & 15)) * LDROW + ((lane >> 4) & 1) * 16;
#pragma unroll
    for (int nq = 0; nq < 2; ++nq)
        bAddr[nq] = sb + OFF_T + 2 * ABYTES + (wn + nq * 16 + (lane & 15)) * LDROW + ((lane >> 4) & 1) * 16;

    float acc[4][4][4];
#pragma unroll
    for (int mb = 0; mb < 4; ++mb)
#pragma unroll
        for (int nb = 0; nb < 4; ++nb)
#pragma unroll
            for (int d = 0; d < 4; ++d) acc[mb][nb][d] = 0.0f;

    // ---- stage loader: Ah, Al, Bh, Bl for one (tap, chunk) ----
    auto load_stage = [&](int q, int st) {
        int tap = q / NCH;
        int c0  = (q - tap * NCH) * 32;

        int srow = row0 + ldr + tap - PAD;
        srow = srow < 0 ? 0 : (srow > NT - 1 ? NT - 1 : srow);
        uint32_t asz = (msk[ldr * KW + tap] != 0.0f) ? 16u : 0u;
        size_t aoff = (size_t)srow * DINP + c0 + ldce;
        uint32_t d = dst0 + st * STG;
        cp_async16(d,               Ah + aoff,     asz);
        cp_async16(d + 16,          Ah + aoff + 8, asz);
        cp_async16(d + ABYTES,      Al + aoff,     asz);
        cp_async16(d + ABYTES + 16, Al + aoff + 8, asz);

        size_t boff = ((size_t)tap * DH + col0 + ldr) * DINP + c0 + ldce;
        uint32_t e = d + 2 * ABYTES;
        cp_async16(e,               Bh + boff,     16u);
        cp_async16(e + 16,          Bh + boff + 8, 16u);
        cp_async16(e + ABYTES,      Bl + boff,     16u);
        cp_async16(e + ABYTES + 16, Bl + boff + 8, 16u);
    };

    // ---- prologue ----
    load_stage(0, 0); cp_commit();

    // ---- mainloop: one __syncthreads per stage; 3 products per stage ----
#pragma unroll 1
    for (int q = 0; q < NQ; ++q) {
        const int st = q & 1;
        cp_wait<0>();
        __syncthreads();                       // stage q visible; slot st^1 free
        if (q + 1 < NQ) load_stage(q + 1, st ^ 1);
        cp_commit();

        const uint32_t so = st * STG;
#pragma unroll
        for (int ks = 0; ks < 2; ++ks) {       // BK=32 -> 2 x k16
            uint32_t afr[4][4], bfh[2][4], bfl[2][4];
#pragma unroll
            for (int mb = 0; mb < 4; ++mb) ldmatrix_x4(afr[mb], aAddr[mb] + so + ks * 32);            // Ah
#pragma unroll
            for (int nq = 0; nq < 2; ++nq) ldmatrix_x4(bfh[nq], bAddr[nq] + so + ks * 32);            // Bh
#pragma unroll
            for (int nq = 0; nq < 2; ++nq) ldmatrix_x4(bfl[nq], bAddr[nq] + so + ABYTES + ks * 32);   // Bl
            // hh: Ah x Bh
#pragma unroll
            for (int mb = 0; mb < 4; ++mb)
#pragma unroll
                for (int nb = 0; nb < 4; ++nb) {
                    int nq = nb >> 1;
                    if (nb & 1) mma_bf16(acc[mb][nb], afr[mb], bfh[nq][1], bfh[nq][3]);
                    else        mma_bf16(acc[mb][nb], afr[mb], bfh[nq][0], bfh[nq][2]);
                }
            // hl: Ah x Bl
#pragma unroll
            for (int mb = 0; mb < 4; ++mb)
#pragma unroll
                for (int nb = 0; nb < 4; ++nb) {
                    int nq = nb >> 1;
                    if (nb & 1) mma_bf16(acc[mb][nb], afr[mb], bfl[nq][1], bfl[nq][3]);
                    else        mma_bf16(acc[mb][nb], afr[mb], bfl[nq][0], bfl[nq][2]);
                }
            // lh: Al x Bh  (afr overwritten with Al fragments)
#pragma unroll
            for (int mb = 0; mb < 4; ++mb) ldmatrix_x4(afr[mb], aAddr[mb] + so + ABYTES + ks * 32);   // Al
#pragma unroll
            for (int mb = 0; mb < 4; ++mb)
#pragma unroll
                for (int nb = 0; nb < 4; ++nb) {
                    int nq = nb >> 1;
                    if (nb & 1) mma_bf16(acc[mb][nb], afr[mb], bfh[nq][1], bfh[nq][3]);
                    else        mma_bf16(acc[mb][nb], afr[mb], bfh[nq][0], bfh[nq][2]);
                }
        }
    }

    // -------- epilogue: y = relu(acc+b)*sc+sh; layer1 emits bf16 split pair --------
    const int erow = lane >> 2;           // 0..7
    const int ecol = (lane & 3) * 2;      // 0,2,4,6
#pragma unroll
    for (int mb = 0; mb < 4; ++mb) {
#pragma unroll
        for (int nb = 0; nb < 4; ++nb) {
#pragma unroll
            for (int half = 0; half < 2; ++half) {
                int r  = row0 + wm + mb * 16 + erow + half * 8;
                int cl = wn + nb * 8 + ecol;            // local col in [0,128)
                float y0 = fmaxf(acc[mb][nb][half * 2 + 0] + sbb[cl],     0.0f) * ssc[cl]     + ssh[cl];
                float y1 = fmaxf(acc[mb][nb][half * 2 + 1] + sbb[cl + 1], 0.0f) * ssc[cl + 1] + ssh[cl + 1];
                if (LAYER == 1) {
                    __nv_bfloat16 h0 = __float2bfloat16(y0);
                    __nv_bfloat16 h1 = __float2bfloat16(y1);
                    __nv_bfloat162 hv; hv.x = h0; hv.y = h1;
                    __nv_bfloat162 lv;
                    lv.x = __float2bfloat16(y0 - __bfloat162float(h0));
                    lv.y = __float2bfloat16(y1 - __bfloat162float(h1));
                    *(__nv_bfloat162*)(g_x2h + (size_t)r * DH + col0 + cl) = hv;
                    *(__nv_bfloat162*)(g_x2l + (size_t)r * DH + col0 + cl) = lv;
                } else {
                    float2 v; v.x = y0; v.y = y1;
                    *(float2*)(g_h2 + (size_t)r * DH + col0 + cl) = v;
                }
            }
        }
    }
}

// ============================================================================
// Head: logits = h2 @ w_lin^T + b_lin ; probs = softmax. One warp per row.
// ============================================================================
__global__ void head_kernel(const float* __restrict__ wlin, const float* __restrict__ blin,
                            float* __restrict__ out, int out_elems)
{
    int gtid = blockIdx.x * blockDim.x + threadIdx.x;
    int row = gtid >> 5, lane = gtid & 31;
    if (row >= NT) return;
    const float* hr = g_h2 + (size_t)row * DH;
    float s0 = 0.0f, s1 = 0.0f;
    for (int j = lane; j < DH; j += 32) {
        float x = hr[j];
        s0 = fmaf(x, wlin[j], s0);
        s1 = fmaf(x, wlin[DH + j], s1);
    }
#pragma unroll
    for (int o = 16; o > 0; o >>= 1) {
        s0 += __shfl_down_sync(0xFFFFFFFFu, s0, o);
        s1 += __shfl_down_sync(0xFFFFFFFFu, s1, o);
    }
    if (lane == 0) {
        float o0 = s0 + blin[0], o1 = s1 + blin[1];
        out[2 * row] = o0;
        out[2 * row + 1] = o1;
        if (out_elems >= 4 * NT) {
            float mx = fmaxf(o0, o1);
            float e0 = expf(o0 - mx), e1 = expf(o1 - mx);
            float inv = 1.0f / (e0 + e1);
            out[2 * NT + 2 * row]     = e0 * inv;
            out[2 * NT + 2 * row + 1] = e1 * inv;
        }
    }
}

// ============================================================================
extern "C" void kernel_launch(void* const* d_in, const int* in_sizes, int n_in,
                              void* d_out, int out_size)
{
    const float* latent = (const float*) d_in[0];
    const int*   seg    = (const int*)   d_in[1];
    const float* w1     = (const float*) d_in[2];
    const float* b1     = (const float*) d_in[3];
    const float* g1     = (const float*) d_in[4];
    const float* be1    = (const float*) d_in[5];
    const float* m1     = (const float*) d_in[6];
    const float* v1     = (const float*) d_in[7];
    const float* w2     = (const float*) d_in[8];
    const float* b2     = (const float*) d_in[9];
    const float* g2     = (const float*) d_in[10];
    const float* be2    = (const float*) d_in[11];
    const float* m2     = (const float*) d_in[12];
    const float* v2     = (const float*) d_in[13];
    const float* wlin   = (const float*) d_in[14];
    const float* blin   = (const float*) d_in[15];
    float*       out    = (float*)       d_out;

    normalize_seg_kernel<<<(NT + 255) / 256, 256>>>(seg);

    size_t nx = (size_t)NT * DINP1;
    split_x_kernel<<<(unsigned)((nx + 255) / 256), 256>>>(latent);
    int nw1 = DH * DINP1;
    int nw2 = DH * DINP2;
    split_w_kernel<<<(nw1 + 255) / 256, 256>>>(w1, DIN1, DINP1, 1, nw1);
    split_w_kernel<<<(nw2 + 255) / 256, 256>>>(w2, DH,   DINP2, 2, nw2);

    cudaFuncSetAttribute(gemm_mma_kernel<DINP1, 1>,
                         cudaFuncAttributeMaxDynamicSharedMemorySize, SM_TOTAL);
    cudaFuncSetAttribute(gemm_mma_kernel<DINP2, 2>,
                         cudaFuncAttributeMaxDynamicSharedMemorySize, SM_TOTAL);

    dim3 grid(NT / 128, DH / 128);   // x fastest -> CTAs sharing a B panel run together
    gemm_mma_kernel<DINP1, 1><<<grid, 256, SM_TOTAL>>>(b1, g1, be1, m1, v1);
    gemm_mma_kernel<DINP2, 2><<<grid, 256, SM_TOTAL>>>(b2, g2, be2, m2, v2);

    head_kernel<<<(NT * 32 + 255) / 256, 256>>>(wlin, blin, out, out_size);
}

// round 15
// speedup vs baseline: 2.2290x; 1.4342x over previous
#include <cuda_runtime.h>
#include <cuda_fp16.h>
#include <math.h>
#include <stdint.h>

// ---------------- problem constants ----------------
#define NT    8192
#define DH    2048
#define KW    9
#define PAD   4
#define DIN1  600
#define DINP1 640      // DIN1 padded to multiple of 32
#define DINP2 2048

// ---------------- device-global scratch (no allocation) ----------------
__device__ int     g_seg[NT];
__device__ __half  g_x1h[(size_t)NT * DINP1];
__device__ __half  g_x1l[(size_t)NT * DINP1];
__device__ __half  g_x2h[(size_t)NT * DH];
__device__ __half  g_x2l[(size_t)NT * DH];
__device__ __half  g_w1h[(size_t)KW * DH * DINP1];
__device__ __half  g_w2h[(size_t)KW * DH * DINP2];
__device__ float   g_h2[(size_t)NT * DH];

// ---------------- helpers ----------------
__device__ __forceinline__ uint32_t smem_u32(const void* p) {
    uint32_t a;
    asm("{ .reg .u64 t; cvta.to.shared.u64 t, %1; cvt.u32.u64 %0, t; }" : "=r"(a) : "l"(p));
    return a;
}
__device__ __forceinline__ void cp_async16(uint32_t dst, const void* src, uint32_t src_bytes) {
    asm volatile("cp.async.cg.shared.global [%0], [%1], 16, %2;"
                 :: "r"(dst), "l"(src), "r"(src_bytes) : "memory");
}
__device__ __forceinline__ void cp_commit() {
    asm volatile("cp.async.commit_group;" ::: "memory");
}
template<int N>
__device__ __forceinline__ void cp_wait() {
    asm volatile("cp.async.wait_group %0;" :: "n"(N) : "memory");
}
__device__ __forceinline__ void ldmatrix_x4(uint32_t* r, uint32_t addr) {
    asm volatile("ldmatrix.sync.aligned.m8n8.x4.shared.b16 {%0,%1,%2,%3}, [%4];"
                 : "=r"(r[0]), "=r"(r[1]), "=r"(r[2]), "=r"(r[3]) : "r"(addr));
}
__device__ __forceinline__ void mma_f16(float* c, const uint32_t* a, uint32_t b0, uint32_t b1) {
    asm volatile("mma.sync.aligned.m16n8k16.row.col.f32.f16.f16.f32 "
                 "{%0,%1,%2,%3}, {%4,%5,%6,%7}, {%8,%9}, {%0,%1,%2,%3};"
                 : "+f"(c[0]), "+f"(c[1]), "+f"(c[2]), "+f"(c[3])
                 : "r"(a[0]), "r"(a[1]), "r"(a[2]), "r"(a[3]), "r"(b0), "r"(b1));
}

// ============================================================================
// Prep kernels
// ============================================================================
__global__ void normalize_seg_kernel(const int* __restrict__ seg32) {
    bool is64 = (seg32[8191] == 0) && (seg32[4097] == 0) && (seg32[6143] == 0);
    int i = blockIdx.x * blockDim.x + threadIdx.x;
    if (i < NT) g_seg[i] = is64 ? seg32[2 * i] : seg32[i];
}

// x fp32 -> fp16 (h, l) pair: x = h + l to ~2^-22
__global__ void split_x_kernel(const float* __restrict__ x) {
    size_t i = (size_t)blockIdx.x * blockDim.x + threadIdx.x;
    if (i >= (size_t)NT * DINP1) return;
    int c = (int)(i % DINP1);
    int r = (int)(i / DINP1);
    float v = (c < DIN1) ? x[(size_t)r * DIN1 + c] : 0.0f;
    __half h = __float2half(v);
    g_x1h[i] = h;
    g_x1l[i] = __float2half(v - __half2float(h));
}

// w [DH, din, KW] -> wh [KW][DH][dinp] fp16 high only (k-contiguous per (tap,n) row)
__global__ void split_w_kernel(const float* __restrict__ w, int din, int dinp, int which, int total) {
    int i = blockIdx.x * blockDim.x + threadIdx.x;   // over DH * dinp
    if (i >= total) return;
    int c = i % dinp;
    int n = i / dinp;
    __half* oh = (which == 1) ? g_w1h : g_w2h;
#pragma unroll
    for (int k = 0; k < KW; ++k) {
        float v = (c < din) ? w[((size_t)n * din + c) * KW + k] : 0.0f;
        oh[((size_t)k * DH + n) * dinp + c] = __float2half(v);
    }
}

// ============================================================================
// mma.sync fp16 2-pass split conv-GEMM, fused bias+ReLU+BN epilogue.
//   out = (Ah + Al) x Bh  (A exact to 2^-22, dropped term A*Bl ~ 2^-11)
//   CTA 128x128, 8 warps as 2(M) x 4(N), warp tile 64x32.
//   Stage = {Ah, Al, Bh} for one (tap, 32-chunk); 2 products per stage.
//   BK=32, 3-stage ring, ONE __syncthreads per stage, wait<1> lookahead.
//   Segment mask via cp.async zero-fill on A.
// ============================================================================
#define LDROW   80                          // (32+8) fp16 = 80B pitch, LDSM conflict-free
#define ABYTES  (128 * LDROW)               // 10240 per tile
#define STG     (3 * ABYTES)                // 30720 per stage (Ah, Al, Bh)
#define NSTAGE  3
#define OFF_MSK 0
#define OFF_SC  4608
#define OFF_SH  5120
#define OFF_BB  5632
#define OFF_T   6144                        // tiles base
#define SM_TOTAL (OFF_T + NSTAGE * STG)     // 98304 B -> 2 CTAs/SM

template<int DINP, int LAYER>
__global__ __launch_bounds__(256, 2)
void gemm_mma_kernel(const float* __restrict__ bias, const float* __restrict__ gam,
                     const float* __restrict__ bet,  const float* __restrict__ mu,
                     const float* __restrict__ var)
{
    constexpr int NCH = DINP / 32;
    constexpr int NQ  = KW * NCH;           // one stage per (tap, chunk)

    extern __shared__ char smem[];
    const uint32_t sb = smem_u32(smem);
    const int tid  = threadIdx.x;
    const int lane = tid & 31;
    const int wid  = tid >> 5;
    const int row0 = blockIdx.x * 128;
    const int col0 = blockIdx.y * 128;

    float* msk = (float*)(smem + OFF_MSK);
    float* ssc = (float*)(smem + OFF_SC);
    float* ssh = (float*)(smem + OFF_SH);
    float* sbb = (float*)(smem + OFF_BB);

    // segment masks + folded BN params
    for (int t = tid; t < 128 * KW; t += 256) {
        int r = t / KW, k = t - r * KW;
        int src = row0 + r + k - PAD;
        msk[r * KW + k] = (src >= 0 && src < NT && g_seg[src] == g_seg[row0 + r]) ? 1.0f : 0.0f;
    }
    if (tid < 128) {
        int n = col0 + tid;
        float s = gam[n] * rsqrtf(var[n] + 1e-5f);
        ssc[tid] = s;
        ssh[tid] = bet[n] - mu[n] * s;
        sbb[tid] = bias[n];
    }
    __syncthreads();

    const __half* Ah = (LAYER == 1) ? g_x1h : g_x2h;
    const __half* Al = (LAYER == 1) ? g_x1l : g_x2l;
    const __half* Bh = (LAYER == 1) ? g_w1h : g_w2h;

    // ---- load mapping: 128 rows x 64B per tile; 2 threads/row, 32B each ----
    const int  ldr   = tid >> 1;              // 0..127
    const int  ldcb  = (tid & 1) * 32;        // byte offset in row
    const int  ldce  = (tid & 1) * 16;        // element offset
    const uint32_t dst0 = sb + OFF_T + ldr * LDROW + ldcb;

    // ---- compute mapping: warps 2(M) x 4(N), warp tile 64x32 ----
    const int wm = (wid >> 2) * 64;
    const int wn = (wid & 3) * 32;
    uint32_t aAddr[4], bAddr[2];
#pragma unroll
    for (int mb = 0; mb < 4; ++mb)
        aAddr[mb] = sb + OFF_T + (wm + mb * 16 + (lane & 15)) * LDROW + ((lane >> 4) & 1) * 16;
#pragma unroll
    for (int nq = 0; nq < 2; ++nq)
        bAddr[nq] = sb + OFF_T + 2 * ABYTES + (wn + nq * 16 + (lane & 15)) * LDROW + ((lane >> 4) & 1) * 16;

    float acc[4][4][4];
#pragma unroll
    for (int mb = 0; mb < 4; ++mb)
#pragma unroll
        for (int nb = 0; nb < 4; ++nb)
#pragma unroll
            for (int d = 0; d < 4; ++d) acc[mb][nb][d] = 0.0f;

    // ---- stage loader: Ah, Al, Bh for one (tap, chunk) ----
    auto load_stage = [&](int q, int st) {
        int tap = q / NCH;
        int c0  = (q - tap * NCH) * 32;

        int srow = row0 + ldr + tap - PAD;
        srow = srow < 0 ? 0 : (srow > NT - 1 ? NT - 1 : srow);
        uint32_t asz = (msk[ldr * KW + tap] != 0.0f) ? 16u : 0u;
        size_t aoff = (size_t)srow * DINP + c0 + ldce;
        uint32_t d = dst0 + st * STG;
        cp_async16(d,               Ah + aoff,     asz);
        cp_async16(d + 16,          Ah + aoff + 8, asz);
        cp_async16(d + ABYTES,      Al + aoff,     asz);
        cp_async16(d + ABYTES + 16, Al + aoff + 8, asz);

        size_t boff = ((size_t)tap * DH + col0 + ldr) * DINP + c0 + ldce;
        uint32_t e = d + 2 * ABYTES;
        cp_async16(e,      Bh + boff,     16u);
        cp_async16(e + 16, Bh + boff + 8, 16u);
    };

    // ---- prologue: fill NSTAGE-1 stages ----
    load_stage(0, 0); cp_commit();
    load_stage(1, 1); cp_commit();

    // ---- mainloop: one __syncthreads per stage; 2 products per stage ----
#pragma unroll 1
    for (int q = 0; q < NQ; ++q) {
        const int st = q % NSTAGE;
        cp_wait<1>();                          // stage q done (newest group = q+1 or tail-empty)
        __syncthreads();                       // slot (q+2)%3 = (q-1)%3 free for reuse
        if (q + 2 < NQ) load_stage(q + 2, (q + 2) % NSTAGE);
        cp_commit();                           // unconditional: keeps wait-count invariant

        const uint32_t so = st * STG;
#pragma unroll
        for (int ks = 0; ks < 2; ++ks) {       // BK=32 -> 2 x k16
            uint32_t afr[4][4], bfh[2][4];
#pragma unroll
            for (int mb = 0; mb < 4; ++mb) ldmatrix_x4(afr[mb], aAddr[mb] + so + ks * 32);           // Ah
#pragma unroll
            for (int nq = 0; nq < 2; ++nq) ldmatrix_x4(bfh[nq], bAddr[nq] + so + ks * 32);           // Bh
            // hh: Ah x Bh
#pragma unroll
            for (int mb = 0; mb < 4; ++mb)
#pragma unroll
                for (int nb = 0; nb < 4; ++nb) {
                    int nq = nb >> 1;
                    if (nb & 1) mma_f16(acc[mb][nb], afr[mb], bfh[nq][1], bfh[nq][3]);
                    else        mma_f16(acc[mb][nb], afr[mb], bfh[nq][0], bfh[nq][2]);
                }
            // lh: Al x Bh  (afr overwritten with Al fragments)
#pragma unroll
            for (int mb = 0; mb < 4; ++mb) ldmatrix_x4(afr[mb], aAddr[mb] + so + ABYTES + ks * 32);  // Al
#pragma unroll
            for (int mb = 0; mb < 4; ++mb)
#pragma unroll
                for (int nb = 0; nb < 4; ++nb) {
                    int nq = nb >> 1;
                    if (nb & 1) mma_f16(acc[mb][nb], afr[mb], bfh[nq][1], bfh[nq][3]);
                    else        mma_f16(acc[mb][nb], afr[mb], bfh[nq][0], bfh[nq][2]);
                }
        }
    }

    // -------- epilogue: y = relu(acc+b)*sc+sh; layer1 emits fp16 split pair --------
    const int erow = lane >> 2;           // 0..7
    const int ecol = (lane & 3) * 2;      // 0,2,4,6
#pragma unroll
    for (int mb = 0; mb < 4; ++mb) {
#pragma unroll
        for (int nb = 0; nb < 4; ++nb) {
#pragma unroll
            for (int half = 0; half < 2; ++half) {
                int r  = row0 + wm + mb * 16 + erow + half * 8;
                int cl = wn + nb * 8 + ecol;            // local col in [0,128)
                float y0 = fmaxf(acc[mb][nb][half * 2 + 0] + sbb[cl],     0.0f) * ssc[cl]     + ssh[cl];
                float y1 = fmaxf(acc[mb][nb][half * 2 + 1] + sbb[cl + 1], 0.0f) * ssc[cl + 1] + ssh[cl + 1];
                if (LAYER == 1) {
                    __half h0 = __float2half(y0);
                    __half h1 = __float2half(y1);
                    __half2 hv; hv.x = h0; hv.y = h1;
                    __half2 lv;
                    lv.x = __float2half(y0 - __half2float(h0));
                    lv.y = __float2half(y1 - __half2float(h1));
                    *(__half2*)(g_x2h + (size_t)r * DH + col0 + cl) = hv;
                    *(__half2*)(g_x2l + (size_t)r * DH + col0 + cl) = lv;
                } else {
                    float2 v; v.x = y0; v.y = y1;
                    *(float2*)(g_h2 + (size_t)r * DH + col0 + cl) = v;
                }
            }
        }
    }
}

// ============================================================================
// Head: logits = h2 @ w_lin^T + b_lin ; probs = softmax. One warp per row.
// ============================================================================
__global__ void head_kernel(const float* __restrict__ wlin, const float* __restrict__ blin,
                            float* __restrict__ out, int out_elems)
{
    int gtid = blockIdx.x * blockDim.x + threadIdx.x;
    int row = gtid >> 5, lane = gtid & 31;
    if (row >= NT) return;
    const float* hr = g_h2 + (size_t)row * DH;
    float s0 = 0.0f, s1 = 0.0f;
    for (int j = lane; j < DH; j += 32) {
        float x = hr[j];
        s0 = fmaf(x, wlin[j], s0);
        s1 = fmaf(x, wlin[DH + j], s1);
    }
#pragma unroll
    for (int o = 16; o > 0; o >>= 1) {
        s0 += __shfl_down_sync(0xFFFFFFFFu, s0, o);
        s1 += __shfl_down_sync(0xFFFFFFFFu, s1, o);
    }
    if (lane == 0) {
        float o0 = s0 + blin[0], o1 = s1 + blin[1];
        out[2 * row] = o0;
        out[2 * row + 1] = o1;
        if (out_elems >= 4 * NT) {
            float mx = fmaxf(o0, o1);
            float e0 = expf(o0 - mx), e1 = expf(o1 - mx);
            float inv = 1.0f / (e0 + e1);
            out[2 * NT + 2 * row]     = e0 * inv;
            out[2 * NT + 2 * row + 1] = e1 * inv;
        }
    }
}

// ============================================================================
extern "C" void kernel_launch(void* const* d_in, const int* in_sizes, int n_in,
                              void* d_out, int out_size)
{
    const float* latent = (const float*) d_in[0];
    const int*   seg    = (const int*)   d_in[1];
    const float* w1     = (const float*) d_in[2];
    const float* b1     = (const float*) d_in[3];
    const float* g1     = (const float*) d_in[4];
    const float* be1    = (const float*) d_in[5];
    const float* m1     = (const float*) d_in[6];
    const float* v1     = (const float*) d_in[7];
    const float* w2     = (const float*) d_in[8];
    const float* b2     = (const float*) d_in[9];
    const float* g2     = (const float*) d_in[10];
    const float* be2    = (const float*) d_in[11];
    const float* m2     = (const float*) d_in[12];
    const float* v2     = (const float*) d_in[13];
    const float* wlin   = (const float*) d_in[14];
    const float* blin   = (const float*) d_in[15];
    float*       out    = (float*)       d_out;

    normalize_seg_kernel<<<(NT + 255) / 256, 256>>>(seg);

    size_t nx = (size_t)NT * DINP1;
    split_x_kernel<<<(unsigned)((nx + 255) / 256), 256>>>(latent);
    int nw1 = DH * DINP1;
    int nw2 = DH * DINP2;
    split_w_kernel<<<(nw1 + 255) / 256, 256>>>(w1, DIN1, DINP1, 1, nw1);
    split_w_kernel<<<(nw2 + 255) / 256, 256>>>(w2, DH,   DINP2, 2, nw2);

    cudaFuncSetAttribute(gemm_mma_kernel<DINP1, 1>,
                         cudaFuncAttributeMaxDynamicSharedMemorySize, SM_TOTAL);
    cudaFuncSetAttribute(gemm_mma_kernel<DINP2, 2>,
                         cudaFuncAttributeMaxDynamicSharedMemorySize, SM_TOTAL);

    dim3 grid(NT / 128, DH / 128);   // x fastest -> CTAs sharing a B panel run together
    gemm_mma_kernel<DINP1, 1><<<grid, 256, SM_TOTAL>>>(b1, g1, be1, m1, v1);
    gemm_mma_kernel<DINP2, 2><<<grid, 256, SM_TOTAL>>>(b2, g2, be2, m2, v2);

    head_kernel<<<(NT * 32 + 255) / 256, 256>>>(wlin, blin, out, out_size);
}